// round 15
// baseline (speedup 1.0000x reference)
#include <cuda_runtime.h>
#include <cstdint>
#include <math.h>

#define NPTS   131072
#define DIM    768
#define KPT    17
#define MPROTO 10
#define KM     170      // KPT*MPROTO
#define KMP    192      // padded columns for GEMM tiling (16 threads * 12 cols)

// ---------------- scratch (__device__ globals; no allocation allowed) --------
__device__ float g_phat[KMP * DIM];     // normalized prototypes, padded rows zero
__device__ float g_rnorm[NPTS];         // 1/max(||feats_n||,1e-12)
__device__ float g_outcls[NPTS * KPT];  // max over m of |sim|
__device__ float g_confeff[NPTS];
__device__ float g_E[NPTS * MPROTO];    // exp(|sim[n, gt_n, m]| / eps)
__device__ float g_cs[3][KM];           // column sums per sinkhorn iter
__device__ float g_c[3][KM];            // column scales per sinkhorn iter
__device__ int   g_B[KPT];              // member counts
__device__ float g_nn[KM];              // n[k,m] counts (sum of conf_eff)
__device__ float g_fbuf[KM * DIM];      // f accumulator
__device__ int   g_sel[NPTS];           // assigned (k*10+m) or -1

struct GKeys { unsigned int a[KPT]; unsigned int b[KPT]; };

// ---------------- threefry2x32 (JAX-compatible, 20 rounds) -------------------
__host__ __device__ inline void threefry2x32(unsigned int k0, unsigned int k1,
                                             unsigned int x0, unsigned int x1,
                                             unsigned int* o0, unsigned int* o1) {
    unsigned int ks[3];
    ks[0] = k0; ks[1] = k1; ks[2] = k0 ^ k1 ^ 0x1BD11BDAu;
    x0 += ks[0]; x1 += ks[1];
    const unsigned int rotA[4] = {13u, 15u, 26u, 6u};
    const unsigned int rotB[4] = {17u, 29u, 16u, 24u};
#pragma unroll
    for (int i = 0; i < 5; i++) {
#pragma unroll
        for (int j = 0; j < 4; j++) {
            unsigned int r = (i & 1) ? rotB[j] : rotA[j];
            x0 += x1;
            x1 = (x1 << r) | (x1 >> (32u - r));
            x1 ^= x0;
        }
        x0 += ks[(i + 1) % 3];
        x1 += ks[(i + 2) % 3] + (unsigned int)(i + 1);
    }
    *o0 = x0; *o1 = x1;
}

__device__ __forceinline__ float gumbel_val(unsigned int ka, unsigned int kb,
                                            unsigned int idx) {
    unsigned int y0, y1;
    threefry2x32(ka, kb, 0u, idx, &y0, &y1);
    unsigned int bits = y0 ^ y1;
    float u = __uint_as_float((bits >> 9) | 0x3F800000u) - 1.0f;
    const float tiny = 1.17549435e-38f;
    u = fmaxf(u + tiny, tiny);
    return -logf(-logf(u));
}

// ---------------- f32x2 packed helpers ---------------------------------------
__device__ __forceinline__ void unpackf2(unsigned long long v, float* x, float* y) {
    asm("mov.b64 {%0, %1}, %2;" : "=f"(*x), "=f"(*y) : "l"(v));
}
__device__ __forceinline__ void ffma2(unsigned long long& acc,
                                      unsigned long long a, unsigned long long b) {
    asm("fma.rn.f32x2 %0, %1, %2, %0;" : "+l"(acc) : "l"(a), "l"(b));
}

// ---------------- block reduction --------------------------------------------
__device__ __forceinline__ float blockReduceSum(float v) {
    __shared__ float sh[33];
    __syncthreads();
    int lane = threadIdx.x & 31, w = threadIdx.x >> 5;
#pragma unroll
    for (int o = 16; o; o >>= 1) v += __shfl_xor_sync(0xffffffffu, v, o);
    if (lane == 0) sh[w] = v;
    __syncthreads();
    int nw = (blockDim.x + 31) >> 5;
    v = (threadIdx.x < nw) ? sh[threadIdx.x] : 0.f;
    if (w == 0) {
#pragma unroll
        for (int o = 16; o; o >>= 1) v += __shfl_xor_sync(0xffffffffu, v, o);
        if (lane == 0) sh[32] = v;
    }
    __syncthreads();
    return sh[32];
}

// ---------------- kernels ----------------------------------------------------
__global__ void k_zero() {
    int i = blockIdx.x * blockDim.x + threadIdx.x;   // 130560 threads
    if (i < KM * DIM) g_fbuf[i] = 0.f;
    if (i < KM) { g_nn[i] = 0.f; g_cs[0][i] = 0.f; g_cs[1][i] = 0.f; g_cs[2][i] = 0.f; }
    if (i < KPT) g_B[i] = 0;
    if (i < (KMP - KM) * DIM) g_phat[KM * DIM + i] = 0.f;   // zero GEMM pad rows
}

__global__ void k_protonorm(const float* __restrict__ protos) {
    int r = blockIdx.x;                 // 0..169
    const float* p = protos + r * DIM;
    float s = 0.f;
    for (int i = threadIdx.x; i < DIM; i += blockDim.x) { float v = p[i]; s += v * v; }
    s = blockReduceSum(s);
    float sc = 1.0f / fmaxf(sqrtf(s), 1e-12f);
    for (int i = threadIdx.x; i < DIM; i += blockDim.x) g_phat[r * DIM + i] = p[i] * sc;
}

__global__ void k_featnorm(const float* __restrict__ feats) {
    int warp = (blockIdx.x * blockDim.x + threadIdx.x) >> 5;
    int lane = threadIdx.x & 31;
    if (warp >= NPTS) return;
    const float4* f = (const float4*)(feats + (size_t)warp * DIM);
    float s = 0.f;
#pragma unroll
    for (int i = 0; i < 6; i++) {
        float4 v = f[lane + i * 32];
        s += v.x * v.x + v.y * v.y + v.z * v.z + v.w * v.w;
    }
#pragma unroll
    for (int o = 16; o; o >>= 1) s += __shfl_xor_sync(0xffffffffu, s, o);
    if (lane == 0) g_rnorm[warp] = 1.0f / fmaxf(sqrtf(s), 1e-12f);
}

// C[N,170] = |(feats . phat^T) * rnorm| using packed FFMA2 (fma.rn.f32x2).
// 8 rows x 12 cols per thread; 256 threads -> 128-row x 192-col block tile.
// Double-buffered smem; A stored as duplicated (a,a) u64 pairs so operands
// come straight out of LDS with zero packing MOVs.
#define TRN 128
#define KC 32
#define AS_STRIDE 68          // floats per A row: 32 k * 2(dup) + 4 pad -> 272B (16B mult)
#define BS_STRIDE 200         // floats per B k-row: 192 + 8 pad -> 800B (16B mult)
#define AS_BUF (TRN * AS_STRIDE)      // 8704 floats
#define BS_BUF (KC * BS_STRIDE)       // 6400 floats
#define GEMM_SMEM ((2 * AS_BUF + 2 * BS_BUF) * 4)   // 120832 bytes

__global__ __launch_bounds__(256, 1) void k_gemm(const float* __restrict__ feats,
                                                 float* __restrict__ out) {
    extern __shared__ float sm[];
    float* Asm = sm;                    // [2][TRN][AS_STRIDE] duplicated pairs
    float* Bsm = sm + 2 * AS_BUF;       // [2][KC][BS_STRIDE]
    int t = threadIdx.x;
    int tx = t & 15;                    // column group (12 cols each)
    int ty = t >> 4;                    // row group (8 rows each)
    int row0 = blockIdx.x * TRN;

    unsigned long long acc[8][6];
#pragma unroll
    for (int r = 0; r < 8; r++)
#pragma unroll
        for (int j = 0; j < 6; j++) acc[r][j] = 0ULL;

    // ---- tile fill helpers (inlined) ----
    auto fillA = [&](int buf, int k0) {
#pragma unroll
        for (int it = 0; it < 4; it++) {
            int id = t + it * 256;          // 0..1023
            int r = id >> 3;
            int q = id & 7;
            float4 v = *(const float4*)(feats + (size_t)(row0 + r) * DIM + k0 + q * 4);
            float* dst = Asm + buf * AS_BUF + r * AS_STRIDE + q * 8;
            *(float4*)(dst)     = make_float4(v.x, v.x, v.y, v.y);
            *(float4*)(dst + 4) = make_float4(v.z, v.z, v.w, v.w);
        }
    };
    auto fillB = [&](int buf, int k0) {
        if (t < KMP) {                      // 192 threads; warp writes 32 consecutive cols
            const float* src = g_phat + (size_t)t * DIM + k0;
            float* base = Bsm + buf * BS_BUF + t;
#pragma unroll
            for (int q = 0; q < 8; q++) {
                float4 v = *(const float4*)(src + q * 4);
                base[(q * 4 + 0) * BS_STRIDE] = v.x;
                base[(q * 4 + 1) * BS_STRIDE] = v.y;
                base[(q * 4 + 2) * BS_STRIDE] = v.z;
                base[(q * 4 + 3) * BS_STRIDE] = v.w;
            }
        }
    };

    fillA(0, 0);
    fillB(0, 0);
    __syncthreads();

    for (int tile = 0; tile < DIM / KC; tile++) {
        int buf = tile & 1;
        if (tile < DIM / KC - 1) {          // prefetch next tile into other buffer
            fillA(buf ^ 1, (tile + 1) * KC);
            fillB(buf ^ 1, (tile + 1) * KC);
        }
        const float* Ab = Asm + buf * AS_BUF + (ty * 8) * AS_STRIDE;
        const float* Bb = Bsm + buf * BS_BUF + tx * 12;
#pragma unroll 8
        for (int kk = 0; kk < KC; kk++) {
            ulonglong2 b0 = *(const ulonglong2*)(Bb + kk * BS_STRIDE);
            ulonglong2 b1 = *(const ulonglong2*)(Bb + kk * BS_STRIDE + 4);
            ulonglong2 b2 = *(const ulonglong2*)(Bb + kk * BS_STRIDE + 8);
#pragma unroll
            for (int r = 0; r < 8; r++) {
                unsigned long long aP =
                    *(const unsigned long long*)(Ab + r * AS_STRIDE + kk * 2);
                ffma2(acc[r][0], aP, b0.x);
                ffma2(acc[r][1], aP, b0.y);
                ffma2(acc[r][2], aP, b1.x);
                ffma2(acc[r][3], aP, b1.y);
                ffma2(acc[r][4], aP, b2.x);
                ffma2(acc[r][5], aP, b2.y);
            }
        }
        __syncthreads();
    }

#pragma unroll
    for (int r = 0; r < 8; r++) {
        int row = row0 + ty * 8 + r;
        float rn = g_rnorm[row];
        float* orow = out + (size_t)row * KM;
#pragma unroll
        for (int j = 0; j < 6; j++) {
            float x, y;
            unpackf2(acc[r][j], &x, &y);
            int col = tx * 12 + 2 * j;
            if (col < KM)     orow[col]     = fabsf(x * rn);
            if (col + 1 < KM) orow[col + 1] = fabsf(y * rn);
        }
    }
}

__global__ void k_outcls(const float* __restrict__ out) {
    int idx = blockIdx.x * blockDim.x + threadIdx.x;
    if (idx >= NPTS * KPT) return;
    int n = idx / KPT, k = idx % KPT;
    const float* p = out + (size_t)n * KM + k * MPROTO;
    float m = p[0];
#pragma unroll
    for (int j = 1; j < MPROTO; j++) m = fmaxf(m, p[j]);
    g_outcls[idx] = m;
}

// per point: pred/conf_eff, kpt_class output, member count, E = exp(sim/eps),
// first sinkhorn column sum (r = 1).
__global__ void k_point(const float* __restrict__ logits, const int* __restrict__ gt,
                        const float* __restrict__ conf, float* __restrict__ d_out) {
    __shared__ float scs[KM];
    for (int i = threadIdx.x; i < KM; i += blockDim.x) scs[i] = 0.f;
    __syncthreads();
    int n = blockIdx.x * blockDim.x + threadIdx.x;    // exact grid
    float best = -1e30f; int pred = 0;
    float* kout = d_out + (size_t)NPTS * KM + NPTS + (size_t)n * KPT;
#pragma unroll
    for (int k = 0; k < KPT; k++) {
        float v = g_outcls[n * KPT + k];
        if (v > best) { best = v; pred = k; }
        kout[k] = fminf(fmaxf(v, 1e-4f), 1.0f - 1e-4f);
    }
    int g = gt[n];
    float ce = (g == pred) ? conf[n] : 0.0f;
    g_confeff[n] = ce;
    atomicAdd(&g_B[g], 1);
    const float* l = logits + (size_t)n * KM + g * MPROTO;
#pragma unroll
    for (int m = 0; m < MPROTO; m++) {
        float e = expf(l[m] / 0.05f);
        g_E[n * MPROTO + m] = e;
        atomicAdd(&scs[g * MPROTO + m], e);
    }
    __syncthreads();
    for (int i = threadIdx.x; i < KM; i += blockDim.x)
        atomicAdd(&g_cs[0][i], scs[i]);
}

__global__ void k_cupdate(int it) {
    int i = threadIdx.x;
    if (i < KM) g_c[it][i] = 1.0f / (10.0f * g_cs[it][i]);
}

// one sinkhorn iteration: row rescale r = 1/(B * sum_m c*E), then next colsum.
__global__ void k_iter(const int* __restrict__ gt, int cin, int cout) {
    __shared__ float sc[KM];
    __shared__ float scs[KM];
    for (int i = threadIdx.x; i < KM; i += blockDim.x) { sc[i] = g_c[cin][i]; scs[i] = 0.f; }
    __syncthreads();
    int n = blockIdx.x * blockDim.x + threadIdx.x;
    int g = gt[n];
    float E[MPROTO], s = 0.f;
#pragma unroll
    for (int m = 0; m < MPROTO; m++) { E[m] = g_E[n * MPROTO + m]; s += sc[g * MPROTO + m] * E[m]; }
    float r = 1.0f / ((float)g_B[g] * s);
#pragma unroll
    for (int m = 0; m < MPROTO; m++) atomicAdd(&scs[g * MPROTO + m], r * E[m]);
    __syncthreads();
    for (int i = threadIdx.x; i < KM; i += blockDim.x) atomicAdd(&g_cs[cout][i], scs[i]);
}

// final L = c3*E / sum(c3*E); idx=argmax L (proto_target); m* = argmax(L+gumbel).
__global__ void k_assign(const int* __restrict__ gt, float* __restrict__ d_out, GKeys keys) {
    __shared__ float sc[KM];
    for (int i = threadIdx.x; i < KM; i += blockDim.x) sc[i] = g_c[2][i];
    __syncthreads();
    int n = blockIdx.x * blockDim.x + threadIdx.x;
    int g = gt[n];
    float v[MPROTO], sv = 0.f, bestv = -1.f;
    int idx = 0;
#pragma unroll
    for (int m = 0; m < MPROTO; m++) {
        float val = sc[g * MPROTO + m] * g_E[n * MPROTO + m];
        v[m] = val; sv += val;
        if (val > bestv) { bestv = val; idx = m; }
    }
    d_out[(size_t)NPTS * KM + n] = (float)(idx + MPROTO * g);

    unsigned int ka = keys.a[g], kb = keys.b[g];
    float bestq = -1e30f; int mb = 0;
#pragma unroll
    for (int m = 0; m < MPROTO; m++) {
        float L = v[m] / sv;
        float q = L + gumbel_val(ka, kb, (unsigned int)(n * MPROTO + m));
        if (q > bestq) { bestq = q; mb = m; }
    }
    float ce = g_confeff[n];
    if (ce > 0.f) {
        atomicAdd(&g_nn[g * MPROTO + mb], ce);
        g_sel[n] = g * MPROTO + mb;
    } else {
        g_sel[n] = -1;
    }
}

// f[k,m,:] += conf_eff^2 * fhat[n,:] for assigned active points (~N/17 active).
__global__ void k_faccum(const float* __restrict__ feats) {
    int warp = (blockIdx.x * blockDim.x + threadIdx.x) >> 5;
    int lane = threadIdx.x & 31;
    if (warp >= NPTS) return;
    int sel = g_sel[warp];
    if (sel < 0) return;
    float ce = g_confeff[warp];
    float w = ce * ce * g_rnorm[warp];
    const float4* f = (const float4*)(feats + (size_t)warp * DIM);
    float* dst = g_fbuf + (size_t)sel * DIM;
#pragma unroll
    for (int i = 0; i < 6; i++) {
        float4 v = f[lane + i * 32];
        int o = (lane + i * 32) * 4;
        atomicAdd(dst + o + 0, w * v.x);
        atomicAdd(dst + o + 1, w * v.y);
        atomicAdd(dst + o + 2, w * v.z);
        atomicAdd(dst + o + 3, w * v.w);
    }
}

// new_protos = l2n(where(has & valid, 0.999*phat + 0.001*l2n(f), phat))
__global__ void k_newprotos(float* __restrict__ d_out) {
    int i = blockIdx.x;                  // 0..169
    int k = i / MPROTO;
    float nnv = g_nn[i];
    float hs = 0.f;
#pragma unroll
    for (int m = 0; m < MPROTO; m++) hs += g_nn[k * MPROTO + m];
    bool cond = (nnv != 0.f) && (hs > 0.f);

    float s = 0.f;
    for (int d = threadIdx.x; d < DIM; d += blockDim.x) { float v = g_fbuf[i * DIM + d]; s += v * v; }
    s = blockReduceSum(s);
    float fs = 1.0f / fmaxf(sqrtf(s), 1e-12f);

    float s2 = 0.f;
    for (int d = threadIdx.x; d < DIM; d += blockDim.x) {
        float p = g_phat[i * DIM + d];
        float b = cond ? 0.999f * p + 0.001f * (g_fbuf[i * DIM + d] * fs) : p;
        s2 += b * b;
    }
    s2 = blockReduceSum(s2);
    float bs = 1.0f / fmaxf(sqrtf(s2), 1e-12f);

    float* o = d_out + (size_t)NPTS * (KM + 1 + KPT) + (size_t)i * DIM;
    for (int d = threadIdx.x; d < DIM; d += blockDim.x) {
        float p = g_phat[i * DIM + d];
        float b = cond ? 0.999f * p + 0.001f * (g_fbuf[i * DIM + d] * fs) : p;
        o[d] = b * bs;
    }
}

// ---------------- launch -----------------------------------------------------
extern "C" void kernel_launch(void* const* d_in, const int* in_sizes, int n_in,
                              void* d_out, int out_size) {
    const float* feats  = (const float*)d_in[0];
    const int*   gt     = (const int*)d_in[1];
    const float* conf   = (const float*)d_in[2];
    const float* protos = (const float*)d_in[3];
    float* out = (float*)d_out;

    GKeys keys;
    for (int k = 0; k < KPT; k++)
        threefry2x32(0u, 42u, 0u, (unsigned int)k, &keys.a[k], &keys.b[k]);

    cudaFuncSetAttribute(k_gemm, cudaFuncAttributeMaxDynamicSharedMemorySize, GEMM_SMEM);

    k_zero<<<(KM * DIM + 255) / 256, 256>>>();
    k_protonorm<<<KM, 256>>>(protos);
    k_featnorm<<<NPTS / 8, 256>>>(feats);
    k_gemm<<<NPTS / TRN, 256, GEMM_SMEM>>>(feats, out);
    k_outcls<<<(NPTS * KPT + 255) / 256, 256>>>(out);
    k_point<<<NPTS / 256, 256>>>(out, gt, conf, out);
    k_cupdate<<<1, 256>>>(0);
    k_iter<<<NPTS / 256, 256>>>(gt, 0, 1);
    k_cupdate<<<1, 256>>>(1);
    k_iter<<<NPTS / 256, 256>>>(gt, 1, 2);
    k_cupdate<<<1, 256>>>(2);
    k_assign<<<NPTS / 256, 256>>>(gt, out, keys);
    k_faccum<<<NPTS / 8, 256>>>(feats);
    k_newprotos<<<KM, 256>>>(out);
}